// round 4
// baseline (speedup 1.0000x reference)
#include <cuda_runtime.h>
#include <math.h>
#include <stdint.h>

// Problem constants
constexpr int B_  = 16;
constexpr int H_  = 1024;
constexpr int CO_ = 512;
constexpr int NV_ = 2048;
constexpr int NQ_ = 2048;

// -------- scratch (device globals; no runtime allocation allowed) --------
__device__ float g_WqQt[(size_t)B_ * CO_ * NQ_];  // 64 MiB
__device__ float g_WvV [(size_t)B_ * CO_ * NV_];  // 64 MiB
__device__ float g_Pv  [(size_t)B_ * CO_ * H_ ];  // 32 MiB
__device__ float g_Rv  [(size_t)B_ * CO_ * H_ ];  // 32 MiB
__device__ float g_Mv  [(size_t)B_ * CO_ * NV_];  // 64 MiB
__device__ float g_Pq  [(size_t)B_ * CO_ * H_ ];  // 32 MiB
__device__ float g_Rq  [(size_t)B_ * CO_ * H_ ];  // 32 MiB
__device__ float g_Mq  [(size_t)B_ * CO_ * NQ_];  // 64 MiB
__device__ float g_logv[(size_t)B_ * NV_];
__device__ float g_logq[(size_t)B_ * NQ_];
__device__ float g_part[(size_t)B_ * 16 * H_];

// packed f32x2 FMA (SASS FFMA2 — only reachable via PTX fma.rn.f32x2)
#define FMA_F32X2(d, a, b) \
    asm("fma.rn.f32x2 %0, %1, %2, %0;" : "+l"(d) : "l"(a), "l"(b))
#define UNPK_F32X2(lo, hi, p) \
    asm("mov.b64 {%0, %1}, %2;" : "=f"(lo), "=f"(hi) : "l"(p))

// ---------------------------------------------------------------------------
// Batched SGEMM via FFMA2: Cm[M,N] = A[M,K] * B, tile 128x128, K-tile 8.
// A row-major [M,K] (lda). BT=false: B is [K,N]; BT=true: B is [N,K].
// grid = (N/128, M/128, batch), 256 threads, 8x8 microtile as 8x(4 pairs).
// ---------------------------------------------------------------------------
template <bool BT>
__global__ __launch_bounds__(256, 2)
void sgemm128(const float* __restrict__ A,  int lda, size_t sA,
              const float* __restrict__ Bm, int ldb, size_t sB,
              float* __restrict__ Cm,       int ldc, size_t sC,
              int K)
{
    __shared__ float As2[8][256];   // A duplicated along M: [k][2m]=[k][2m+1]=A[m][k]
    __shared__ float Bs[8][128];

    const int tid = threadIdx.x;
    const int bx = blockIdx.x, by = blockIdx.y, bz = blockIdx.z;

    A  += (size_t)bz * sA + (size_t)(by * 128) * lda;
    Bm += (size_t)bz * sB;
    Cm += (size_t)bz * sC + (size_t)(by * 128) * ldc + (size_t)bx * 128;

    const int arow = tid >> 1;          // 0..127
    const int ak4  = (tid & 1) * 4;     // 0 or 4
    const int bkrow = tid >> 5;         // 0..7
    const int bcol4 = (tid & 31) * 4;   // 0..124

    const int tx = tid & 15;
    const int ty = tid >> 4;

    unsigned long long acc[8][4];
#pragma unroll
    for (int i = 0; i < 8; ++i)
#pragma unroll
        for (int p = 0; p < 4; ++p) acc[i][p] = 0ull;

    for (int k0 = 0; k0 < K; k0 += 8) {
        // stage A tile duplicated: As2[k][2m], As2[k][2m+1] = A[m][k]
        float4 av = *reinterpret_cast<const float4*>(A + (size_t)arow * lda + k0 + ak4);
        *reinterpret_cast<float2*>(&As2[ak4 + 0][2 * arow]) = make_float2(av.x, av.x);
        *reinterpret_cast<float2*>(&As2[ak4 + 1][2 * arow]) = make_float2(av.y, av.y);
        *reinterpret_cast<float2*>(&As2[ak4 + 2][2 * arow]) = make_float2(av.z, av.z);
        *reinterpret_cast<float2*>(&As2[ak4 + 3][2 * arow]) = make_float2(av.w, av.w);

        if (BT) {
            const float4 bv = *reinterpret_cast<const float4*>(
                Bm + (size_t)(bx * 128 + arow) * ldb + k0 + ak4);
            Bs[ak4 + 0][arow] = bv.x;
            Bs[ak4 + 1][arow] = bv.y;
            Bs[ak4 + 2][arow] = bv.z;
            Bs[ak4 + 3][arow] = bv.w;
        } else {
            const float4 bv = *reinterpret_cast<const float4*>(
                Bm + (size_t)(k0 + bkrow) * ldb + (size_t)bx * 128 + bcol4);
            *reinterpret_cast<float4*>(&Bs[bkrow][bcol4]) = bv;
        }
        __syncthreads();

#pragma unroll
        for (int kk = 0; kk < 8; ++kk) {
            unsigned long long aa[8], bp[4];
            const unsigned long long* ap0 =
                reinterpret_cast<const unsigned long long*>(&As2[kk][8 * ty]);
            const unsigned long long* ap1 =
                reinterpret_cast<const unsigned long long*>(&As2[kk][128 + 8 * ty]);
#pragma unroll
            for (int i = 0; i < 4; ++i) { aa[i] = ap0[i]; aa[4 + i] = ap1[i]; }
            const unsigned long long* bq0 =
                reinterpret_cast<const unsigned long long*>(&Bs[kk][tx * 4]);
            const unsigned long long* bq1 =
                reinterpret_cast<const unsigned long long*>(&Bs[kk][64 + tx * 4]);
            bp[0] = bq0[0]; bp[1] = bq0[1]; bp[2] = bq1[0]; bp[3] = bq1[1];
#pragma unroll
            for (int i = 0; i < 8; ++i)
#pragma unroll
                for (int p = 0; p < 4; ++p)
                    FMA_F32X2(acc[i][p], aa[i], bp[p]);
        }
        __syncthreads();
    }

#pragma unroll
    for (int i = 0; i < 8; ++i) {
        const int r = (i < 4) ? (ty * 4 + i) : (64 + ty * 4 + (i - 4));
        float4 c0, c1;
        UNPK_F32X2(c0.x, c0.y, acc[i][0]);
        UNPK_F32X2(c0.z, c0.w, acc[i][1]);
        UNPK_F32X2(c1.x, c1.y, acc[i][2]);
        UNPK_F32X2(c1.z, c1.w, acc[i][3]);
        *reinterpret_cast<float4*>(Cm + (size_t)r * ldc + tx * 4)      = c0;
        *reinterpret_cast<float4*>(Cm + (size_t)r * ldc + 64 + tx * 4) = c1;
    }
}

// ---------------------------------------------------------------------------
// logits[b, n] = sum_c w[c] * tanh(X[b,c,n] + Y[b,c,n])
// ---------------------------------------------------------------------------
__global__ void logits_kernel(const float* __restrict__ X,
                              const float* __restrict__ Y,
                              const float* __restrict__ w,
                              float* __restrict__ lg, int Ncol)
{
    __shared__ float ws[CO_];
    const int tid = threadIdx.x;
    for (int c = tid; c < CO_; c += blockDim.x) ws[c] = w[c];
    __syncthreads();

    const int b = blockIdx.y;
    const int n = blockIdx.x * blockDim.x + tid;
    size_t idx = ((size_t)b * CO_) * Ncol + n;
    float acc = 0.f;
#pragma unroll 4
    for (int c = 0; c < CO_; ++c) {
        acc += ws[c] * tanhf(X[idx] + Y[idx]);
        idx += Ncol;
    }
    lg[(size_t)b * Ncol + n] = acc;
}

// ---------------------------------------------------------------------------
// softmax over Ncol (=2048) per batch; grid = B, block = 256
// ---------------------------------------------------------------------------
__global__ void softmax_kernel(const float* __restrict__ lg,
                               float* __restrict__ outp, int Ncol)
{
    __shared__ float buf[2048];
    __shared__ float red[256];
    const int b = blockIdx.x;
    const int tid = threadIdx.x;
    const float* x = lg + (size_t)b * Ncol;

    float mx = -INFINITY;
    for (int i = tid; i < Ncol; i += 256) {
        float v = x[i];
        buf[i] = v;
        mx = fmaxf(mx, v);
    }
    red[tid] = mx;
    __syncthreads();
    for (int s = 128; s > 0; s >>= 1) {
        if (tid < s) red[tid] = fmaxf(red[tid], red[tid + s]);
        __syncthreads();
    }
    mx = red[0];
    __syncthreads();

    float sm = 0.f;
    for (int i = tid; i < Ncol; i += 256) {
        float e = expf(buf[i] - mx);
        buf[i] = e;
        sm += e;
    }
    red[tid] = sm;
    __syncthreads();
    for (int s = 128; s > 0; s >>= 1) {
        if (tid < s) red[tid] += red[tid + s];
        __syncthreads();
    }
    const float inv = 1.f / red[0];
    for (int i = tid; i < Ncol; i += 256)
        outp[(size_t)b * Ncol + i] = buf[i] * inv;
}

// ---------------------------------------------------------------------------
// v[b,h] = sum_v a[b,v] * V[b,h,v]; warp per h row. grid=(H/8, B), block=256
// ---------------------------------------------------------------------------
__global__ void av_V_kernel(const float* __restrict__ a,
                            const float* __restrict__ V,
                            float* __restrict__ outv)
{
    const int b = blockIdx.y;
    const int h = blockIdx.x * 8 + (threadIdx.x >> 5);
    const int lane = threadIdx.x & 31;
    const float* row = V + ((size_t)b * H_ + h) * NV_;
    const float* av = a + (size_t)b * NV_;
    float acc = 0.f;
    for (int i = lane; i < NV_; i += 32) acc += av[i] * row[i];
#pragma unroll
    for (int off = 16; off > 0; off >>= 1)
        acc += __shfl_down_sync(0xffffffffu, acc, off);
    if (lane == 0) outv[(size_t)b * H_ + h] = acc;
}

// ---------------------------------------------------------------------------
// q[b,h] = sum_q a[b,q] * Q[b,q,h]; deterministic 2-stage reduction
// ---------------------------------------------------------------------------
__global__ void aq_Q_partial(const float* __restrict__ a,
                             const float* __restrict__ Q,
                             float* __restrict__ part)
{
    const int b = blockIdx.y, j = blockIdx.x;
    const int h = threadIdx.x;
    const float* aq = a + (size_t)b * NQ_;
    float acc = 0.f;
    const int q0 = j * (NQ_ / 16);
    for (int q = q0; q < q0 + NQ_ / 16; ++q)
        acc += aq[q] * Q[((size_t)b * NQ_ + q) * H_ + h];
    part[((size_t)b * 16 + j) * H_ + h] = acc;
}

__global__ void aq_Q_reduce(const float* __restrict__ part,
                            float* __restrict__ outq)
{
    const int b = blockIdx.x;
    const int h = threadIdx.x;
    float acc = 0.f;
#pragma unroll
    for (int j = 0; j < 16; ++j)
        acc += part[((size_t)b * 16 + j) * H_ + h];
    outq[(size_t)b * H_ + h] = acc;
}

// ---------------------------------------------------------------------------
extern "C" void kernel_launch(void* const* d_in, const int* in_sizes, int n_in,
                              void* d_out, int out_size)
{
    const float* V    = (const float*)d_in[0];  // [B, H, NV]
    const float* Q    = (const float*)d_in[1];  // [B, NQ, H]
    const float* W_b  = (const float*)d_in[2];  // [H, H]
    const float* W_v  = (const float*)d_in[3];  // [CO, H]
    const float* W_q  = (const float*)d_in[4];  // [CO, H]
    const float* w_hv = (const float*)d_in[5];  // [CO, 1]
    const float* w_hq = (const float*)d_in[6];  // [CO, 1]
    float* out = (float*)d_out;

    float *WqQt, *WvV, *Pv, *Rv, *Mv, *Pq, *Rq, *Mq, *logv, *logq, *part;
    cudaGetSymbolAddress((void**)&WqQt, g_WqQt);
    cudaGetSymbolAddress((void**)&WvV,  g_WvV);
    cudaGetSymbolAddress((void**)&Pv,   g_Pv);
    cudaGetSymbolAddress((void**)&Rv,   g_Rv);
    cudaGetSymbolAddress((void**)&Mv,   g_Mv);
    cudaGetSymbolAddress((void**)&Pq,   g_Pq);
    cudaGetSymbolAddress((void**)&Rq,   g_Rq);
    cudaGetSymbolAddress((void**)&Mq,   g_Mq);
    cudaGetSymbolAddress((void**)&logv, g_logv);
    cudaGetSymbolAddress((void**)&logq, g_logq);
    cudaGetSymbolAddress((void**)&part, g_part);

    const size_t sQ  = (size_t)NQ_ * H_;
    const size_t sV  = (size_t)H_ * NV_;
    const size_t sCN = (size_t)CO_ * NV_;
    const size_t sCH = (size_t)CO_ * H_;

    // 1. WqQt[b] = W_q @ Q[b]^T         [CO, NQ], K=H
    sgemm128<true ><<<dim3(NQ_/128, CO_/128, B_), 256>>>(W_q, H_, 0, Q, H_, sQ, WqQt, NQ_, sCN, H_);
    // 2. WvV[b] = W_v @ V[b]            [CO, NV], K=H
    sgemm128<false><<<dim3(NV_/128, CO_/128, B_), 256>>>(W_v, H_, 0, V, NV_, sV, WvV, NV_, sCN, H_);
    // 3. Pv[b] = WqQt[b] @ Q[b]         [CO, H], K=NQ
    sgemm128<false><<<dim3(H_/128, CO_/128, B_), 256>>>(WqQt, NQ_, sCN, Q, H_, sQ, Pv, H_, sCH, NQ_);
    // 4. Rv[b] = Pv[b] @ W_b            [CO, H], K=H
    sgemm128<false><<<dim3(H_/128, CO_/128, B_), 256>>>(Pv, H_, sCH, W_b, H_, 0, Rv, H_, sCH, H_);
    // 5. Mv[b] = Rv[b] @ V[b]           [CO, NV], K=H
    sgemm128<false><<<dim3(NV_/128, CO_/128, B_), 256>>>(Rv, H_, sCH, V, NV_, sV, Mv, NV_, sCN, H_);
    // 6. Pq[b] = WvV[b] @ V[b]^T        [CO, H], K=NV
    sgemm128<true ><<<dim3(H_/128, CO_/128, B_), 256>>>(WvV, NV_, sCN, V, NV_, sV, Pq, H_, sCH, NV_);
    // 7. Rq[b] = Pq[b] @ W_b^T          [CO, H], K=H
    sgemm128<true ><<<dim3(H_/128, CO_/128, B_), 256>>>(Pq, H_, sCH, W_b, H_, 0, Rq, H_, sCH, H_);
    // 8. Mq[b] = Rq[b] @ Q[b]^T         [CO, NQ], K=H
    sgemm128<true ><<<dim3(NQ_/128, CO_/128, B_), 256>>>(Rq, H_, sCH, Q, H_, sQ, Mq, NQ_, sCN, H_);

    // logits + softmax
    logits_kernel<<<dim3(NV_/256, B_), 256>>>(WvV,  Mv, w_hv, logv, NV_);
    logits_kernel<<<dim3(NQ_/256, B_), 256>>>(WqQt, Mq, w_hq, logq, NQ_);

    float* out_av = out;                                  // [B,1,NV]
    float* out_aq = out + (size_t)B_ * NV_;               // [B,1,NQ]
    float* out_v  = out + (size_t)B_ * (NV_ + NQ_);       // [B,H]
    float* out_q  = out_v + (size_t)B_ * H_;              // [B,H]

    softmax_kernel<<<B_, 256>>>(logv, out_av, NV_);
    softmax_kernel<<<B_, 256>>>(logq, out_aq, NQ_);

    av_V_kernel<<<dim3(H_/8, B_), 256>>>(out_av, V, out_v);
    aq_Q_partial<<<dim3(16, B_), 1024>>>(out_aq, Q, part);
    aq_Q_reduce<<<B_, 1024>>>(part, out_q);
}

// round 5
// speedup vs baseline: 1.4392x; 1.4392x over previous
#include <cuda_runtime.h>
#include <math.h>
#include <stdint.h>

constexpr int B_  = 16;
constexpr int H_  = 1024;
constexpr int CO_ = 512;
constexpr int NV_ = 2048;
constexpr int NQ_ = 2048;

// -------- scratch (device globals) --------
__device__ float g_Qt [(size_t)B_ * H_ * NQ_];   // Q^T per batch [H, NQ]
__device__ float g_Vt [(size_t)B_ * NV_ * H_];   // V^T per batch [NV, H]
__device__ float g_WqT[(size_t)H_ * CO_];
__device__ float g_WvT[(size_t)H_ * CO_];
__device__ float g_Wbt[(size_t)H_ * H_];
__device__ float g_T1 [(size_t)B_ * NQ_ * CO_];  // WqQt^T  [NQ, CO]
__device__ float g_T2 [(size_t)B_ * NV_ * CO_];  // WvV^T   [NV, CO]
__device__ float g_PvT[(size_t)B_ * H_ * CO_];
__device__ float g_RvT[(size_t)B_ * H_ * CO_];
__device__ float g_MvT[(size_t)B_ * NV_ * CO_];
__device__ float g_PqT[(size_t)B_ * H_ * CO_];
__device__ float g_RqT[(size_t)B_ * H_ * CO_];
__device__ float g_MqT[(size_t)B_ * NQ_ * CO_];
__device__ float g_logv[(size_t)B_ * NV_];
__device__ float g_logq[(size_t)B_ * NQ_];

__device__ __forceinline__ uint32_t smem_u32(const void* p) {
    uint32_t a;
    asm("{ .reg .u64 t; cvta.to.shared.u64 t, %1; cvt.u32.u64 %0, t; }" : "=r"(a) : "l"(p));
    return a;
}
#define CPA16(dst, src) \
    asm volatile("cp.async.cg.shared.global [%0], [%1], 16;" :: "r"(dst), "l"(src))
#define CP_COMMIT() asm volatile("cp.async.commit_group;" ::: "memory")
#define CP_WAIT1()  asm volatile("cp.async.wait_group 1;" ::: "memory")

// ---------------------------------------------------------------------------
// C[M,512] = A^T * B.  A[K,M] k-major (lda = global M), B[K,512] (ldb=512).
// Tile 128x128, K-tile 16, 3-stage cp.async pipeline, 256 thr, 8x8 microtile.
// grid = (4, M/128, batch)
// ---------------------------------------------------------------------------
__global__ __launch_bounds__(256, 2)
void gemm_atb(const float* __restrict__ A, int lda, size_t sA,
              const float* __restrict__ Bm, size_t sB,
              float* __restrict__ Cm, size_t sC, int K)
{
    __shared__ float As[3][16][128];
    __shared__ float Bs[3][16][128];

    const int tid = threadIdx.x;
    const int bx = blockIdx.x, by = blockIdx.y, bz = blockIdx.z;

    const float* gA = A + (size_t)bz * sA + bx * 0 + by * 128;
    const float* gB = Bm + (size_t)bz * sB + bx * 128;
    float* gC = Cm + (size_t)bz * sC + (size_t)(by * 128) * 512 + bx * 128;

    const int row0 = tid >> 5;          // 0..7 (chunk rows; +8 for second chunk)
    const int col  = (tid & 31) * 4;    // float offset within row

    const uint32_t saB = smem_u32(&As[0][0][0]);
    const uint32_t sbB = smem_u32(&Bs[0][0][0]);
    const uint32_t dA0 = saB + (uint32_t)(row0 * 128 + col) * 4;
    const uint32_t dB0 = sbB + (uint32_t)(row0 * 128 + col) * 4;

    const int tx = tid & 15, ty = tid >> 4;
    const int T = K >> 4;

    float acc[8][8];
#pragma unroll
    for (int i = 0; i < 8; ++i)
#pragma unroll
        for (int j = 0; j < 8; ++j) acc[i][j] = 0.f;

    // prologue: stages 0..2
#pragma unroll
    for (int s = 0; s < 3; ++s) {
        const size_t kr = (size_t)(s * 16 + row0);
        CPA16(dA0 + s * 8192,        gA + kr * lda + col);
        CPA16(dA0 + s * 8192 + 4096, gA + (kr + 8) * lda + col);
        CPA16(dB0 + s * 8192,        gB + kr * 512 + col);
        CPA16(dB0 + s * 8192 + 4096, gB + (kr + 8) * 512 + col);
        CP_COMMIT();
    }

    int buf = 0;
    for (int t = 0; t < T; ++t) {
        CP_WAIT1();
        __syncthreads();

        const float (*Ab)[128] = As[buf];
        const float (*Bb)[128] = Bs[buf];
#pragma unroll
        for (int kk = 0; kk < 16; ++kk) {
            const float4 a0 = *reinterpret_cast<const float4*>(&Ab[kk][ty * 4]);
            const float4 a1 = *reinterpret_cast<const float4*>(&Ab[kk][64 + ty * 4]);
            const float4 b0 = *reinterpret_cast<const float4*>(&Bb[kk][tx * 4]);
            const float4 b1 = *reinterpret_cast<const float4*>(&Bb[kk][64 + tx * 4]);
            const float a[8] = {a0.x, a0.y, a0.z, a0.w, a1.x, a1.y, a1.z, a1.w};
            const float b[8] = {b0.x, b0.y, b0.z, b0.w, b1.x, b1.y, b1.z, b1.w};
#pragma unroll
            for (int i = 0; i < 8; ++i)
#pragma unroll
                for (int j = 0; j < 8; ++j)
                    acc[i][j] = fmaf(a[i], b[j], acc[i][j]);
        }
        __syncthreads();

        if (t + 3 < T) {
            const size_t kr = (size_t)((t + 3) * 16 + row0);
            CPA16(dA0 + buf * 8192,        gA + kr * lda + col);
            CPA16(dA0 + buf * 8192 + 4096, gA + (kr + 8) * lda + col);
            CPA16(dB0 + buf * 8192,        gB + kr * 512 + col);
            CPA16(dB0 + buf * 8192 + 4096, gB + (kr + 8) * 512 + col);
        }
        CP_COMMIT();
        buf = (buf == 2) ? 0 : buf + 1;
    }

#pragma unroll
    for (int i = 0; i < 8; ++i) {
        const int r = (i < 4) ? (ty * 4 + i) : (64 + ty * 4 + (i - 4));
        *reinterpret_cast<float4*>(gC + (size_t)r * 512 + tx * 4) =
            make_float4(acc[i][0], acc[i][1], acc[i][2], acc[i][3]);
        *reinterpret_cast<float4*>(gC + (size_t)r * 512 + 64 + tx * 4) =
            make_float4(acc[i][4], acc[i][5], acc[i][6], acc[i][7]);
    }
}

// ---------------- transpose: src[bz][R][Cc] -> dst[bz][Cc][R] --------------
__global__ void transpose_k(const float* __restrict__ src, float* __restrict__ dst,
                            int R, int Cc)
{
    __shared__ float tile[32][33];
    const float* s = src + (size_t)blockIdx.z * R * Cc;
    float* d = dst + (size_t)blockIdx.z * R * Cc;
    const int x = blockIdx.x * 32 + threadIdx.x;
    for (int j = threadIdx.y; j < 32; j += 8)
        tile[j][threadIdx.x] = s[(size_t)(blockIdx.y * 32 + j) * Cc + x];
    __syncthreads();
    const int x2 = blockIdx.y * 32 + threadIdx.x;
    for (int j = threadIdx.y; j < 32; j += 8)
        d[(size_t)(blockIdx.x * 32 + j) * R + x2] = tile[threadIdx.x][j];
}

// -------- logits[b,n] = sum_c w[c]*tanh(X[b,n,c]+Y[b,n,c]); warp per n -----
__global__ void logits_t(const float* __restrict__ X, const float* __restrict__ Y,
                         const float* __restrict__ w, float* __restrict__ lg, int Ncol)
{
    const int b = blockIdx.y;
    const int n = blockIdx.x * 8 + (threadIdx.x >> 5);
    const int lane = threadIdx.x & 31;
    const float* xp = X + ((size_t)b * Ncol + n) * CO_;
    const float* yp = Y + ((size_t)b * Ncol + n) * CO_;
    float acc = 0.f;
#pragma unroll 4
    for (int c = lane; c < CO_; c += 32)
        acc += w[c] * tanhf(xp[c] + yp[c]);
#pragma unroll
    for (int off = 16; off > 0; off >>= 1)
        acc += __shfl_down_sync(0xffffffffu, acc, off);
    if (lane == 0) lg[(size_t)b * Ncol + n] = acc;
}

// ---------------- softmax over Ncol per batch; grid=B, block=256 -----------
__global__ void softmax_kernel(const float* __restrict__ lg, float* __restrict__ outp, int Ncol)
{
    __shared__ float buf[2048];
    __shared__ float red[256];
    const int b = blockIdx.x, tid = threadIdx.x;
    const float* x = lg + (size_t)b * Ncol;
    float mx = -INFINITY;
    for (int i = tid; i < Ncol; i += 256) { float v = x[i]; buf[i] = v; mx = fmaxf(mx, v); }
    red[tid] = mx; __syncthreads();
    for (int s = 128; s > 0; s >>= 1) { if (tid < s) red[tid] = fmaxf(red[tid], red[tid + s]); __syncthreads(); }
    mx = red[0]; __syncthreads();
    float sm = 0.f;
    for (int i = tid; i < Ncol; i += 256) { float e = expf(buf[i] - mx); buf[i] = e; sm += e; }
    red[tid] = sm; __syncthreads();
    for (int s = 128; s > 0; s >>= 1) { if (tid < s) red[tid] += red[tid + s]; __syncthreads(); }
    const float inv = 1.f / red[0];
    for (int i = tid; i < Ncol; i += 256) outp[(size_t)b * Ncol + i] = buf[i] * inv;
}

// ------ out[b,h] = sum_n a[b,n]*X[b,h,n]; warp per h. grid=(H/8,B) ---------
__global__ void wdot_kernel(const float* __restrict__ a, const float* __restrict__ X,
                            float* __restrict__ outv, int Ncol)
{
    const int b = blockIdx.y;
    const int h = blockIdx.x * 8 + (threadIdx.x >> 5);
    const int lane = threadIdx.x & 31;
    const float* row = X + ((size_t)b * H_ + h) * Ncol;
    const float* av = a + (size_t)b * Ncol;
    float acc = 0.f;
    for (int i = lane; i < Ncol; i += 32) acc += av[i] * row[i];
#pragma unroll
    for (int off = 16; off > 0; off >>= 1) acc += __shfl_down_sync(0xffffffffu, acc, off);
    if (lane == 0) outv[(size_t)b * H_ + h] = acc;
}

// ---------------------------------------------------------------------------
extern "C" void kernel_launch(void* const* d_in, const int* in_sizes, int n_in,
                              void* d_out, int out_size)
{
    const float* V    = (const float*)d_in[0];  // [B, H, NV]
    const float* Q    = (const float*)d_in[1];  // [B, NQ, H]
    const float* W_b  = (const float*)d_in[2];  // [H, H]
    const float* W_v  = (const float*)d_in[3];  // [CO, H]
    const float* W_q  = (const float*)d_in[4];  // [CO, H]
    const float* w_hv = (const float*)d_in[5];
    const float* w_hq = (const float*)d_in[6];
    float* out = (float*)d_out;

    float *Qt, *Vt, *WqT, *WvT, *Wbt, *T1, *T2, *PvT, *RvT, *MvT, *PqT, *RqT, *MqT, *logv, *logq;
    cudaGetSymbolAddress((void**)&Qt,  g_Qt);
    cudaGetSymbolAddress((void**)&Vt,  g_Vt);
    cudaGetSymbolAddress((void**)&WqT, g_WqT);
    cudaGetSymbolAddress((void**)&WvT, g_WvT);
    cudaGetSymbolAddress((void**)&Wbt, g_Wbt);
    cudaGetSymbolAddress((void**)&T1,  g_T1);
    cudaGetSymbolAddress((void**)&T2,  g_T2);
    cudaGetSymbolAddress((void**)&PvT, g_PvT);
    cudaGetSymbolAddress((void**)&RvT, g_RvT);
    cudaGetSymbolAddress((void**)&MvT, g_MvT);
    cudaGetSymbolAddress((void**)&PqT, g_PqT);
    cudaGetSymbolAddress((void**)&RqT, g_RqT);
    cudaGetSymbolAddress((void**)&MqT, g_MqT);
    cudaGetSymbolAddress((void**)&logv, g_logv);
    cudaGetSymbolAddress((void**)&logq, g_logq);

    const size_t sQ  = (size_t)NQ_ * H_;    // Q / Qt per-batch stride
    const size_t sV  = (size_t)H_ * NV_;    // V / Vt per-batch stride
    const size_t sNC = (size_t)NQ_ * CO_;   // [2048, 512]
    const size_t sHC = (size_t)H_ * CO_;    // [1024, 512]

    // pre-transposes
    transpose_k<<<dim3(H_/32, NQ_/32, B_), dim3(32, 8)>>>(Q, Qt, NQ_, H_);    // Qt [H,NQ]
    transpose_k<<<dim3(NV_/32, H_/32, B_), dim3(32, 8)>>>(V, Vt, H_, NV_);    // Vt [NV,H]
    transpose_k<<<dim3(H_/32, CO_/32, 1),  dim3(32, 8)>>>(W_q, WqT, CO_, H_); // [H,CO]
    transpose_k<<<dim3(H_/32, CO_/32, 1),  dim3(32, 8)>>>(W_v, WvT, CO_, H_); // [H,CO]
    transpose_k<<<dim3(H_/32, H_/32, 1),   dim3(32, 8)>>>(W_b, Wbt, H_, H_);  // [H,H]

    // All GEMMs: C[M,512] = A^T B, grid (4, M/128, 16)
    // 1. T1 = Qt^T·WqT      [NQ,CO]  K=H
    gemm_atb<<<dim3(4, NQ_/128, B_), 256>>>(Qt, NQ_, sQ, WqT, 0, T1, sNC, H_);
    // 2. T2 = V^T·WvT       [NV,CO]  K=H
    gemm_atb<<<dim3(4, NV_/128, B_), 256>>>(V, NV_, sV, WvT, 0, T2, sNC, H_);
    // 3. PvT = Q^T·T1       [H,CO]   K=NQ
    gemm_atb<<<dim3(4, H_/128, B_), 256>>>(Q, H_, sQ, T1, sNC, PvT, sHC, NQ_);
    // 4. RvT = W_b^T·PvT    [H,CO]   K=H
    gemm_atb<<<dim3(4, H_/128, B_), 256>>>(W_b, H_, 0, PvT, sHC, RvT, sHC, H_);
    // 5. MvT = V^T·RvT      [NV,CO]  K=H
    gemm_atb<<<dim3(4, NV_/128, B_), 256>>>(V, NV_, sV, RvT, sHC, MvT, sNC, H_);
    // 6. PqT = Vt^T·T2      [H,CO]   K=NV
    gemm_atb<<<dim3(4, H_/128, B_), 256>>>(Vt, H_, sV, T2, sNC, PqT, sHC, NV_);
    // 7. RqT = Wbt^T·PqT    [H,CO]   K=H
    gemm_atb<<<dim3(4, H_/128, B_), 256>>>(Wbt, H_, 0, PqT, sHC, RqT, sHC, H_);
    // 8. MqT = Qt^T·RqT     [NQ,CO]  K=H
    gemm_atb<<<dim3(4, NQ_/128, B_), 256>>>(Qt, NQ_, sQ, RqT, sHC, MqT, sNC, H_);

    // logits (transposed layout), softmax, weighted sums
    logits_t<<<dim3(NV_/8, B_), 256>>>(T2, MvT, w_hv, logv, NV_);
    logits_t<<<dim3(NQ_/8, B_), 256>>>(T1, MqT, w_hq, logq, NQ_);

    float* out_av = out;
    float* out_aq = out + (size_t)B_ * NV_;
    float* out_v  = out + (size_t)B_ * (NV_ + NQ_);
    float* out_q  = out_v + (size_t)B_ * H_;

    softmax_kernel<<<B_, 256>>>(logv, out_av, NV_);
    softmax_kernel<<<B_, 256>>>(logq, out_aq, NQ_);

    wdot_kernel<<<dim3(H_/8, B_), 256>>>(out_av, V,  out_v, NV_);
    wdot_kernel<<<dim3(H_/8, B_), 256>>>(out_aq, Qt, out_q, NQ_);
}

// round 6
// speedup vs baseline: 1.5687x; 1.0899x over previous
#include <cuda_runtime.h>
#include <math.h>
#include <stdint.h>

constexpr int B_  = 16;
constexpr int H_  = 1024;
constexpr int CO_ = 512;
constexpr int NV_ = 2048;
constexpr int NQ_ = 2048;

// -------- scratch (device globals) --------
__device__ float g_Qt [(size_t)B_ * H_ * NQ_];
__device__ float g_Vt [(size_t)B_ * NV_ * H_];
__device__ float g_WqT[(size_t)H_ * CO_];
__device__ float g_WvT[(size_t)H_ * CO_];
__device__ float g_Wbt[(size_t)H_ * H_];
__device__ float g_T1 [(size_t)B_ * NQ_ * CO_];
__device__ float g_T2 [(size_t)B_ * NV_ * CO_];
__device__ float g_PvT[(size_t)B_ * H_ * CO_];
__device__ float g_RvT[(size_t)B_ * H_ * CO_];
__device__ float g_MvT[(size_t)B_ * NV_ * CO_];
__device__ float g_PqT[(size_t)B_ * H_ * CO_];
__device__ float g_RqT[(size_t)B_ * H_ * CO_];
__device__ float g_MqT[(size_t)B_ * NQ_ * CO_];
__device__ float g_logv[(size_t)B_ * NV_];
__device__ float g_logq[(size_t)B_ * NQ_];

__device__ __forceinline__ uint32_t smem_u32(const void* p) {
    uint32_t a;
    asm("{ .reg .u64 t; cvta.to.shared.u64 t, %1; cvt.u32.u64 %0, t; }" : "=r"(a) : "l"(p));
    return a;
}
#define CPA16(dst, src) \
    asm volatile("cp.async.cg.shared.global [%0], [%1], 16;" :: "r"(dst), "l"(src))
#define CP_COMMIT() asm volatile("cp.async.commit_group;" ::: "memory")
#define CP_WAIT1()  asm volatile("cp.async.wait_group 1;" ::: "memory")

// split fp32 into tf32 hi + tf32(lo) (3xTF32 decomposition)
__device__ __forceinline__ void split_tf32(float x, uint32_t& h, uint32_t& l) {
    asm("cvt.rna.tf32.f32 %0, %1;" : "=r"(h) : "f"(x));
    const float lf = x - __uint_as_float(h);
    asm("cvt.rna.tf32.f32 %0, %1;" : "=r"(l) : "f"(lf));
}
__device__ __forceinline__ void mma8(float* c, const uint32_t* a, const uint32_t* b) {
    asm volatile(
        "mma.sync.aligned.m16n8k8.row.col.f32.tf32.tf32.f32 "
        "{%0,%1,%2,%3}, {%4,%5,%6,%7}, {%8,%9}, {%0,%1,%2,%3};"
        : "+f"(c[0]), "+f"(c[1]), "+f"(c[2]), "+f"(c[3])
        : "r"(a[0]), "r"(a[1]), "r"(a[2]), "r"(a[3]), "r"(b[0]), "r"(b[1]));
}

// ---------------------------------------------------------------------------
// C[M,512] = A^T * B via tf32 mma (3xTF32).  A[K,M] k-major, B[K,512] k-major.
// Block tile 128x128, 8 warps (2x4) of 64x32, K-slab 32, 3-stage cp.async.
// Smem rows padded to 136 floats (conflict-free fragment LDS).
// grid = (4, M/128, batch), 256 threads.
// ---------------------------------------------------------------------------
constexpr int SROW = 136;                       // floats per smem row
constexpr int STG_F = 2 * 32 * SROW;            // floats per stage (A+B) = 8704
constexpr int SMEM_MMA = 3 * STG_F * 4;         // 104448 bytes

__global__ __launch_bounds__(256, 2)
void gemm_mma(const float* __restrict__ A, int lda, size_t sA,
              const float* __restrict__ Bm, size_t sB,
              float* __restrict__ Cm, size_t sC, int K)
{
    extern __shared__ __align__(16) float sm[];
    const int tid = threadIdx.x;
    const int bx = blockIdx.x, by = blockIdx.y, bz = blockIdx.z;

    const float* gA = A + (size_t)bz * sA + by * 128;
    const float* gB = Bm + (size_t)bz * sB + bx * 128;
    float* gC = Cm + (size_t)bz * sC + (size_t)(by * 128) * 512 + bx * 128;

    const int lane = tid & 31, w = tid >> 5;
    const int g = lane >> 2, t = lane & 3;
    const int rbase = (w & 1) * 64;      // warp row offset within 128
    const int cbase = (w >> 1) * 32;     // warp col offset within 128

    const uint32_t smb = smem_u32(sm);
    const int srow = tid >> 5;           // staging base row (0..7), +8/+16/+24 via it
    const int scol = (tid & 31) * 4;

    float c[4][4][4];
#pragma unroll
    for (int i = 0; i < 4; ++i)
#pragma unroll
        for (int j = 0; j < 4; ++j)
#pragma unroll
            for (int k = 0; k < 4; ++k) c[i][j][k] = 0.f;

    const int T = K >> 5;

    // prologue: stages 0..2
#pragma unroll
    for (int s = 0; s < 3; ++s) {
        const uint32_t ab = smb + (uint32_t)s * (STG_F * 4);
        const uint32_t bb = ab + 32 * SROW * 4;
        const int k0 = s * 32;
#pragma unroll
        for (int it = 0; it < 4; ++it) {
            const int row = srow + it * 8;
            CPA16(ab + (uint32_t)(row * SROW + scol) * 4, gA + (size_t)(k0 + row) * lda + scol);
            CPA16(bb + (uint32_t)(row * SROW + scol) * 4, gB + (size_t)(k0 + row) * 512 + scol);
        }
        CP_COMMIT();
    }

    int buf = 0;
    for (int tt = 0; tt < T; ++tt) {
        CP_WAIT1();
        __syncthreads();

        const float* Ab = sm + buf * STG_F;
        const float* Bb = Ab + 32 * SROW;
#pragma unroll
        for (int ks = 0; ks < 4; ++ks) {
            const float* ap = Ab + (ks * 8 + t) * SROW;
            const float* bp = Bb + (ks * 8 + t) * SROW;
            uint32_t ah[4][4], al[4][4], bh[4][2], bl[4][2];
#pragma unroll
            for (int i = 0; i < 4; ++i) {
                const int m = rbase + i * 16 + g;
                split_tf32(ap[m],            ah[i][0], al[i][0]);
                split_tf32(ap[m + 8],        ah[i][1], al[i][1]);
                split_tf32(ap[4 * SROW + m],     ah[i][2], al[i][2]);
                split_tf32(ap[4 * SROW + m + 8], ah[i][3], al[i][3]);
            }
#pragma unroll
            for (int j = 0; j < 4; ++j) {
                const int n = cbase + j * 8 + g;
                split_tf32(bp[n],            bh[j][0], bl[j][0]);
                split_tf32(bp[4 * SROW + n], bh[j][1], bl[j][1]);
            }
#pragma unroll
            for (int i = 0; i < 4; ++i)
#pragma unroll
                for (int j = 0; j < 4; ++j) {
                    mma8(c[i][j], ah[i], bl[j]);
                    mma8(c[i][j], al[i], bh[j]);
                    mma8(c[i][j], ah[i], bh[j]);
                }
        }
        __syncthreads();

        if (tt + 3 < T) {
            const uint32_t ab = smb + (uint32_t)buf * (STG_F * 4);
            const uint32_t bb = ab + 32 * SROW * 4;
            const int k0 = (tt + 3) * 32;
#pragma unroll
            for (int it = 0; it < 4; ++it) {
                const int row = srow + it * 8;
                CPA16(ab + (uint32_t)(row * SROW + scol) * 4, gA + (size_t)(k0 + row) * lda + scol);
                CPA16(bb + (uint32_t)(row * SROW + scol) * 4, gB + (size_t)(k0 + row) * 512 + scol);
            }
        }
        CP_COMMIT();
        buf = (buf == 2) ? 0 : buf + 1;
    }

    // epilogue: c frags -> global (float2 per quad-row, 32B sectors)
#pragma unroll
    for (int i = 0; i < 4; ++i) {
        const int r0 = rbase + i * 16 + g;
#pragma unroll
        for (int j = 0; j < 4; ++j) {
            const int cc = cbase + j * 8 + 2 * t;
            *reinterpret_cast<float2*>(gC + (size_t)r0 * 512 + cc) =
                make_float2(c[i][j][0], c[i][j][1]);
            *reinterpret_cast<float2*>(gC + (size_t)(r0 + 8) * 512 + cc) =
                make_float2(c[i][j][2], c[i][j][3]);
        }
    }
}

// ---------------- transpose: src[bz][R][Cc] -> dst[bz][Cc][R] --------------
__global__ void transpose_k(const float* __restrict__ src, float* __restrict__ dst,
                            int R, int Cc)
{
    __shared__ float tile[32][33];
    const float* s = src + (size_t)blockIdx.z * R * Cc;
    float* d = dst + (size_t)blockIdx.z * R * Cc;
    const int x = blockIdx.x * 32 + threadIdx.x;
    for (int j = threadIdx.y; j < 32; j += 8)
        tile[j][threadIdx.x] = s[(size_t)(blockIdx.y * 32 + j) * Cc + x];
    __syncthreads();
    const int x2 = blockIdx.y * 32 + threadIdx.x;
    for (int j = threadIdx.y; j < 32; j += 8)
        d[(size_t)(blockIdx.x * 32 + j) * R + x2] = tile[threadIdx.x][j];
}

// -------- logits[b,n] = sum_c w[c]*tanh(X[b,n,c]+Y[b,n,c]); warp per n -----
__global__ void logits_t(const float* __restrict__ X, const float* __restrict__ Y,
                         const float* __restrict__ w, float* __restrict__ lg, int Ncol)
{
    const int b = blockIdx.y;
    const int n = blockIdx.x * 8 + (threadIdx.x >> 5);
    const int lane = threadIdx.x & 31;
    const float* xp = X + ((size_t)b * Ncol + n) * CO_;
    const float* yp = Y + ((size_t)b * Ncol + n) * CO_;
    float acc = 0.f;
#pragma unroll 4
    for (int c = lane; c < CO_; c += 32)
        acc += w[c] * tanhf(xp[c] + yp[c]);
#pragma unroll
    for (int off = 16; off > 0; off >>= 1)
        acc += __shfl_down_sync(0xffffffffu, acc, off);
    if (lane == 0) lg[(size_t)b * Ncol + n] = acc;
}

// ---------------- softmax over Ncol per batch; grid=B, block=256 -----------
__global__ void softmax_kernel(const float* __restrict__ lg, float* __restrict__ outp, int Ncol)
{
    __shared__ float buf[2048];
    __shared__ float red[256];
    const int b = blockIdx.x, tid = threadIdx.x;
    const float* x = lg + (size_t)b * Ncol;
    float mx = -INFINITY;
    for (int i = tid; i < Ncol; i += 256) { float v = x[i]; buf[i] = v; mx = fmaxf(mx, v); }
    red[tid] = mx; __syncthreads();
    for (int s = 128; s > 0; s >>= 1) { if (tid < s) red[tid] = fmaxf(red[tid], red[tid + s]); __syncthreads(); }
    mx = red[0]; __syncthreads();
    float sm = 0.f;
    for (int i = tid; i < Ncol; i += 256) { float e = expf(buf[i] - mx); buf[i] = e; sm += e; }
    red[tid] = sm; __syncthreads();
    for (int s = 128; s > 0; s >>= 1) { if (tid < s) red[tid] += red[tid + s]; __syncthreads(); }
    const float inv = 1.f / red[0];
    for (int i = tid; i < Ncol; i += 256) outp[(size_t)b * Ncol + i] = buf[i] * inv;
}

// ------ out[b,h] = sum_n a[b,n]*X[b,h,n]; warp per h. grid=(H/8,B) ---------
__global__ void wdot_kernel(const float* __restrict__ a, const float* __restrict__ X,
                            float* __restrict__ outv, int Ncol)
{
    const int b = blockIdx.y;
    const int h = blockIdx.x * 8 + (threadIdx.x >> 5);
    const int lane = threadIdx.x & 31;
    const float* row = X + ((size_t)b * H_ + h) * Ncol;
    const float* av = a + (size_t)b * Ncol;
    float acc = 0.f;
    for (int i = lane; i < Ncol; i += 32) acc += av[i] * row[i];
#pragma unroll
    for (int off = 16; off > 0; off >>= 1) acc += __shfl_down_sync(0xffffffffu, acc, off);
    if (lane == 0) outv[(size_t)b * H_ + h] = acc;
}

// ---------------------------------------------------------------------------
extern "C" void kernel_launch(void* const* d_in, const int* in_sizes, int n_in,
                              void* d_out, int out_size)
{
    const float* V    = (const float*)d_in[0];  // [B, H, NV]
    const float* Q    = (const float*)d_in[1];  // [B, NQ, H]
    const float* W_b  = (const float*)d_in[2];  // [H, H]
    const float* W_v  = (const float*)d_in[3];  // [CO, H]
    const float* W_q  = (const float*)d_in[4];  // [CO, H]
    const float* w_hv = (const float*)d_in[5];
    const float* w_hq = (const float*)d_in[6];
    float* out = (float*)d_out;

    float *Qt, *Vt, *WqT, *WvT, *Wbt, *T1, *T2, *PvT, *RvT, *MvT, *PqT, *RqT, *MqT, *logv, *logq;
    cudaGetSymbolAddress((void**)&Qt,  g_Qt);
    cudaGetSymbolAddress((void**)&Vt,  g_Vt);
    cudaGetSymbolAddress((void**)&WqT, g_WqT);
    cudaGetSymbolAddress((void**)&WvT, g_WvT);
    cudaGetSymbolAddress((void**)&Wbt, g_Wbt);
    cudaGetSymbolAddress((void**)&T1,  g_T1);
    cudaGetSymbolAddress((void**)&T2,  g_T2);
    cudaGetSymbolAddress((void**)&PvT, g_PvT);
    cudaGetSymbolAddress((void**)&RvT, g_RvT);
    cudaGetSymbolAddress((void**)&MvT, g_MvT);
    cudaGetSymbolAddress((void**)&PqT, g_PqT);
    cudaGetSymbolAddress((void**)&RqT, g_RqT);
    cudaGetSymbolAddress((void**)&MqT, g_MqT);
    cudaGetSymbolAddress((void**)&logv, g_logv);
    cudaGetSymbolAddress((void**)&logq, g_logq);

    cudaFuncSetAttribute(gemm_mma, cudaFuncAttributeMaxDynamicSharedMemorySize, SMEM_MMA);

    const size_t sQ  = (size_t)NQ_ * H_;
    const size_t sV  = (size_t)H_ * NV_;
    const size_t sNC = (size_t)NQ_ * CO_;
    const size_t sHC = (size_t)H_ * CO_;

    transpose_k<<<dim3(H_/32, NQ_/32, B_), dim3(32, 8)>>>(Q, Qt, NQ_, H_);
    transpose_k<<<dim3(NV_/32, H_/32, B_), dim3(32, 8)>>>(V, Vt, H_, NV_);
    transpose_k<<<dim3(H_/32, CO_/32, 1),  dim3(32, 8)>>>(W_q, WqT, CO_, H_);
    transpose_k<<<dim3(H_/32, CO_/32, 1),  dim3(32, 8)>>>(W_v, WvT, CO_, H_);
    transpose_k<<<dim3(H_/32, H_/32, 1),   dim3(32, 8)>>>(W_b, Wbt, H_, H_);

    // 1. T1 = Qt^T·WqT      [NQ,CO]  K=H
    gemm_mma<<<dim3(4, NQ_/128, B_), 256, SMEM_MMA>>>(Qt, NQ_, sQ, WqT, 0, T1, sNC, H_);
    // 2. T2 = V^T·WvT       [NV,CO]  K=H
    gemm_mma<<<dim3(4, NV_/128, B_), 256, SMEM_MMA>>>(V, NV_, sV, WvT, 0, T2, sNC, H_);
    // 3. PvT = Q^T·T1       [H,CO]   K=NQ
    gemm_mma<<<dim3(4, H_/128, B_), 256, SMEM_MMA>>>(Q, H_, sQ, T1, sNC, PvT, sHC, NQ_);
    // 4. RvT = W_b^T·PvT    [H,CO]   K=H
    gemm_mma<<<dim3(4, H_/128, B_), 256, SMEM_MMA>>>(W_b, H_, 0, PvT, sHC, RvT, sHC, H_);
    // 5. MvT = V^T·RvT      [NV,CO]  K=H
    gemm_mma<<<dim3(4, NV_/128, B_), 256, SMEM_MMA>>>(V, NV_, sV, RvT, sHC, MvT, sNC, H_);
    // 6. PqT = Vt^T·T2      [H,CO]   K=NV
    gemm_mma<<<dim3(4, H_/128, B_), 256, SMEM_MMA>>>(Vt, H_, sV, T2, sNC, PqT, sHC, NV_);
    // 7. RqT = Wbt^T·PqT    [H,CO]   K=H
    gemm_mma<<<dim3(4, H_/128, B_), 256, SMEM_MMA>>>(Wbt, H_, 0, PqT, sHC, RqT, sHC, H_);
    // 8. MqT = Qt^T·RqT     [NQ,CO]  K=H
    gemm_mma<<<dim3(4, NQ_/128, B_), 256, SMEM_MMA>>>(Qt, NQ_, sQ, RqT, sHC, MqT, sNC, H_);

    logits_t<<<dim3(NV_/8, B_), 256>>>(T2, MvT, w_hv, logv, NV_);
    logits_t<<<dim3(NQ_/8, B_), 256>>>(T1, MqT, w_hq, logq, NQ_);

    float* out_av = out;
    float* out_aq = out + (size_t)B_ * NV_;
    float* out_v  = out + (size_t)B_ * (NV_ + NQ_);
    float* out_q  = out_v + (size_t)B_ * H_;

    softmax_kernel<<<B_, 256>>>(logv, out_av, NV_);
    softmax_kernel<<<B_, 256>>>(logq, out_aq, NQ_);

    wdot_kernel<<<dim3(H_/8, B_), 256>>>(out_av, V,  out_v, NV_);
    wdot_kernel<<<dim3(H_/8, B_), 256>>>(out_aq, Qt, out_q, NQ_);
}